// round 13
// baseline (speedup 1.0000x reference)
#include <cuda_runtime.h>

// Problem constants (from reference setup_inputs)
#define B_    256
#define J_    17
#define HW_   6912            // 96*72
#define V4_   (HW_ / 4)       // 1728 float4 per (b,j) slice
#define BJ_   (B_ * J_)       // 4352
#define TPB_  288             // 1728 / 288 = exactly 6 iterations per slice
#define SPC_  2               // slices per CTA
#define GRIDA (BJ_ / SPC_)    // 2176 blocks

// Scratch: transposed partials, g_partials[j * B_ + b] (contiguous per joint)
__device__ float g_partials[BJ_];

// ---------------------------------------------------------------------------
// Kernel A: two (b,j) slices per CTA, 288 threads, exact 6-iter unrolled
// stream per slice with evict-first loads and independent accumulator chains.
// PDL trigger fired at entry; weight loads hoisted to overlap the stream.
// ---------------------------------------------------------------------------
__global__ __launch_bounds__(TPB_) void jmse_partial_kernel(
    const float* __restrict__ out,
    const float* __restrict__ tgt,
    const float* __restrict__ wgt)
{
    asm volatile("griddepcontrol.launch_dependents;");

    const int bj0 = blockIdx.x * SPC_;       // first slice
    const int bj1 = bj0 + 1;                 // second slice

    // Hoisted scalar weight loads: resolved long before the epilogue.
    float w0 = 0.0f, w1 = 0.0f;
    if (threadIdx.x == 0) {
        w0 = __ldg(&wgt[bj0]);
        w1 = __ldg(&wgt[bj1]);
    }

    const float4* __restrict__ o0 = (const float4*)(out + (size_t)bj0 * HW_);
    const float4* __restrict__ t0 = (const float4*)(tgt + (size_t)bj0 * HW_);
    const float4* __restrict__ o1 = (const float4*)(out + (size_t)bj1 * HW_);
    const float4* __restrict__ t1 = (const float4*)(tgt + (size_t)bj1 * HW_);

    // Independent per-slice accumulator chains (also doubles load ILP).
    float acc0 = 0.0f, acc1 = 0.0f;
    #pragma unroll
    for (int k = 0; k < 6; k++) {            // exact: 6 * 288 = 1728 per slice
        const int i = threadIdx.x + k * TPB_;
        float4 a0 = __ldcs(o0 + i);          // single-use stream: evict-first
        float4 b0 = __ldcs(t0 + i);
        float4 a1 = __ldcs(o1 + i);
        float4 b1 = __ldcs(t1 + i);

        float d0 = a0.x - b0.x;
        float d1 = a0.y - b0.y;
        float d2 = a0.z - b0.z;
        float d3 = a0.w - b0.w;
        acc0 = fmaf(d0, d0, acc0);
        acc0 = fmaf(d1, d1, acc0);
        acc0 = fmaf(d2, d2, acc0);
        acc0 = fmaf(d3, d3, acc0);

        float e0 = a1.x - b1.x;
        float e1 = a1.y - b1.y;
        float e2 = a1.z - b1.z;
        float e3 = a1.w - b1.w;
        acc1 = fmaf(e0, e0, acc1);
        acc1 = fmaf(e1, e1, acc1);
        acc1 = fmaf(e2, e2, acc1);
        acc1 = fmaf(e3, e3, acc1);
    }

    // warp reduce both accumulators
    #pragma unroll
    for (int off = 16; off > 0; off >>= 1) {
        acc0 += __shfl_xor_sync(0xFFFFFFFFu, acc0, off);
        acc1 += __shfl_xor_sync(0xFFFFFFFFu, acc1, off);
    }

    __shared__ float warp_sums0[TPB_ / 32];  // 9 warps
    __shared__ float warp_sums1[TPB_ / 32];
    const int lane = threadIdx.x & 31;
    const int wid  = threadIdx.x >> 5;
    if (lane == 0) {
        warp_sums0[wid] = acc0;
        warp_sums1[wid] = acc1;
    }
    __syncthreads();

    if (threadIdx.x == 0) {
        float s0 = 0.0f, s1 = 0.0f;
        #pragma unroll
        for (int w9 = 0; w9 < TPB_ / 32; w9++) {
            s0 += warp_sums0[w9];
            s1 += warp_sums1[w9];
        }
        const int b0i = bj0 / J_;
        const int j0  = bj0 - b0i * J_;
        const int b1i = bj1 / J_;
        const int j1  = bj1 - b1i * J_;
        g_partials[j0 * B_ + b0i] = s0 * w0 * w0;   // transposed stores
        g_partials[j1 * B_ + b1i] = s1 * w1 * w1;
    }
}

// ---------------------------------------------------------------------------
// Kernel B (PDL secondary): 17 warps, one per joint; contiguous float4 loads.
// topk prefetched before the parked wait (independent of A's data).
// ---------------------------------------------------------------------------
__global__ __launch_bounds__(544) void jmse_final_kernel(
    const int* __restrict__ topk_ptr,
    float* __restrict__ result)
{
    __shared__ float losses[J_];
    __shared__ int   s_k;
    const int wid  = threadIdx.x >> 5;   // 0..16
    const int lane = threadIdx.x & 31;

    // Prefetch top_k while parked: does not depend on kernel A's writes.
    if (threadIdx.x == 0) s_k = *topk_ptr;

    // Park until primary grid completes; its writes are then visible.
    asm volatile("griddepcontrol.wait;");

    if (wid < J_) {
        // 256 floats per joint = 64 float4, 2 per lane
        const float4* p4 = (const float4*)&g_partials[wid * B_];
        float4 a = p4[lane];
        float4 b = p4[lane + 32];
        float s = (a.x + a.y) + (a.z + a.w) + (b.x + b.y) + (b.z + b.w);
        #pragma unroll
        for (int off = 16; off > 0; off >>= 1)
            s += __shfl_xor_sync(0xFFFFFFFFu, s, off);
        if (lane == 0)
            losses[wid] = s * (1.0f / ((float)B_ * (float)HW_));
    }
    __syncthreads();

    if (threadIdx.x == 0) {
        const int k = s_k;
        float v[J_];
        #pragma unroll
        for (int j = 0; j < J_; j++) v[j] = losses[j];
        float sum = 0.0f;
        for (int s = 0; s < k; s++) {
            int   best_i = 0;
            float best_v = v[0];
            #pragma unroll
            for (int j = 1; j < J_; j++)
                if (v[j] > best_v) { best_v = v[j]; best_i = j; }
            sum += best_v;
            v[best_i] = -3.402823466e38f;
        }
        result[0] = sum / (float)k;
    }
}

// ---------------------------------------------------------------------------
extern "C" void kernel_launch(void* const* d_in, const int* in_sizes, int n_in,
                              void* d_out, int out_size)
{
    const float* out_t = (const float*)d_in[0];
    const float* tgt_t = (const float*)d_in[1];
    const float* wgt_t = (const float*)d_in[2];
    const int*   topk  = (const int*)d_in[3];
    float* res = (float*)d_out;

    jmse_partial_kernel<<<GRIDA, TPB_>>>(out_t, tgt_t, wgt_t);

    cudaLaunchConfig_t cfg = {};
    cfg.gridDim  = dim3(1, 1, 1);
    cfg.blockDim = dim3(544, 1, 1);
    cfg.dynamicSmemBytes = 0;
    cfg.stream = 0;
    cudaLaunchAttribute attr[1];
    attr[0].id = cudaLaunchAttributeProgrammaticStreamSerialization;
    attr[0].val.programmaticStreamSerializationAllowed = 1;
    cfg.attrs = attr;
    cfg.numAttrs = 1;
    cudaLaunchKernelEx(&cfg, jmse_final_kernel, topk, res);
}

// round 14
// speedup vs baseline: 1.0117x; 1.0117x over previous
#include <cuda_runtime.h>

// Problem constants (from reference setup_inputs)
#define B_    256
#define J_    17
#define HW_   6912            // 96*72
#define V4_   (HW_ / 4)       // 1728 float4 per (b,j) slice
#define BJ_   (B_ * J_)       // 4352
#define TPB_  288             // 1728 / 288 = exactly 6 iterations, no ragged tail

// Scratch: transposed partials, g_partials[j * B_ + b] (contiguous per joint)
__device__ float g_partials[BJ_];

// ---------------------------------------------------------------------------
// Kernel A: one block per (b,j) slice, 288 threads, exact 6-iter unrolled
// stream with evict-first (__ldcs) loads. PDL trigger fired at entry;
// weight load hoisted to overlap the stream.  [R12 configuration — best]
// ---------------------------------------------------------------------------
__global__ __launch_bounds__(TPB_) void jmse_partial_kernel(
    const float* __restrict__ out,
    const float* __restrict__ tgt,
    const float* __restrict__ wgt)
{
    asm volatile("griddepcontrol.launch_dependents;");

    const int bj = blockIdx.x;

    // Hoisted scalar weight load: resolved long before the epilogue.
    float w_early = 0.0f;
    if (threadIdx.x == 0) w_early = __ldg(&wgt[bj]);

    const size_t base = (size_t)bj * HW_;
    const float4* __restrict__ o4 = (const float4*)(out + base);
    const float4* __restrict__ t4 = (const float4*)(tgt + base);

    // Two independent accumulator chains (even/odd unroll steps).
    float acc0 = 0.0f, acc1 = 0.0f;
    #pragma unroll
    for (int k = 0; k < 6; k++) {          // exact: 6 * 288 = 1728
        const int i = threadIdx.x + k * TPB_;
        float4 a = __ldcs(o4 + i);         // single-use stream: evict-first
        float4 b = __ldcs(t4 + i);
        float d0 = a.x - b.x;
        float d1 = a.y - b.y;
        float d2 = a.z - b.z;
        float d3 = a.w - b.w;
        if (k & 1) {
            acc1 = fmaf(d0, d0, acc1);
            acc1 = fmaf(d1, d1, acc1);
            acc1 = fmaf(d2, d2, acc1);
            acc1 = fmaf(d3, d3, acc1);
        } else {
            acc0 = fmaf(d0, d0, acc0);
            acc0 = fmaf(d1, d1, acc0);
            acc0 = fmaf(d2, d2, acc0);
            acc0 = fmaf(d3, d3, acc0);
        }
    }
    float acc = acc0 + acc1;

    // warp reduce
    #pragma unroll
    for (int off = 16; off > 0; off >>= 1)
        acc += __shfl_xor_sync(0xFFFFFFFFu, acc, off);

    __shared__ float warp_sums[TPB_ / 32];   // 9 warps
    const int lane = threadIdx.x & 31;
    const int wid  = threadIdx.x >> 5;
    if (lane == 0) warp_sums[wid] = acc;
    __syncthreads();

    if (threadIdx.x == 0) {
        float s = 0.0f;
        #pragma unroll
        for (int w9 = 0; w9 < TPB_ / 32; w9++) s += warp_sums[w9];
        const int b = bj / J_;
        const int j = bj - b * J_;
        g_partials[j * B_ + b] = s * w_early * w_early;   // transposed store
    }
}

// ---------------------------------------------------------------------------
// Kernel B (PDL secondary): 17 warps, one per joint; contiguous float4 loads.
// topk prefetched before the parked wait (independent of A's data).
// ---------------------------------------------------------------------------
__global__ __launch_bounds__(544) void jmse_final_kernel(
    const int* __restrict__ topk_ptr,
    float* __restrict__ result)
{
    __shared__ float losses[J_];
    __shared__ int   s_k;
    const int wid  = threadIdx.x >> 5;   // 0..16
    const int lane = threadIdx.x & 31;

    // Prefetch top_k while parked: does not depend on kernel A's writes.
    if (threadIdx.x == 0) s_k = *topk_ptr;

    // Park until primary grid completes; its writes are then visible.
    asm volatile("griddepcontrol.wait;");

    if (wid < J_) {
        // 256 floats per joint = 64 float4, 2 per lane
        const float4* p4 = (const float4*)&g_partials[wid * B_];
        float4 a = p4[lane];
        float4 b = p4[lane + 32];
        float s = (a.x + a.y) + (a.z + a.w) + (b.x + b.y) + (b.z + b.w);
        #pragma unroll
        for (int off = 16; off > 0; off >>= 1)
            s += __shfl_xor_sync(0xFFFFFFFFu, s, off);
        if (lane == 0)
            losses[wid] = s * (1.0f / ((float)B_ * (float)HW_));
    }
    __syncthreads();

    if (threadIdx.x == 0) {
        const int k = s_k;
        float v[J_];
        #pragma unroll
        for (int j = 0; j < J_; j++) v[j] = losses[j];
        float sum = 0.0f;
        for (int s = 0; s < k; s++) {
            int   best_i = 0;
            float best_v = v[0];
            #pragma unroll
            for (int j = 1; j < J_; j++)
                if (v[j] > best_v) { best_v = v[j]; best_i = j; }
            sum += best_v;
            v[best_i] = -3.402823466e38f;
        }
        result[0] = sum / (float)k;
    }
}

// ---------------------------------------------------------------------------
extern "C" void kernel_launch(void* const* d_in, const int* in_sizes, int n_in,
                              void* d_out, int out_size)
{
    const float* out_t = (const float*)d_in[0];
    const float* tgt_t = (const float*)d_in[1];
    const float* wgt_t = (const float*)d_in[2];
    const int*   topk  = (const int*)d_in[3];
    float* res = (float*)d_out;

    jmse_partial_kernel<<<BJ_, TPB_>>>(out_t, tgt_t, wgt_t);

    cudaLaunchConfig_t cfg = {};
    cfg.gridDim  = dim3(1, 1, 1);
    cfg.blockDim = dim3(544, 1, 1);
    cfg.dynamicSmemBytes = 0;
    cfg.stream = 0;
    cudaLaunchAttribute attr[1];
    attr[0].id = cudaLaunchAttributeProgrammaticStreamSerialization;
    attr[0].val.programmaticStreamSerializationAllowed = 1;
    cfg.attrs = attr;
    cfg.numAttrs = 1;
    cudaLaunchKernelEx(&cfg, jmse_final_kernel, topk, res);
}

// round 15
// speedup vs baseline: 1.0125x; 1.0008x over previous
#include <cuda_runtime.h>

// Problem constants (from reference setup_inputs)
#define B_    256
#define J_    17
#define HW_   6912            // 96*72
#define V4_   (HW_ / 4)       // 1728 float4 per (b,j) slice
#define BJ_   (B_ * J_)       // 4352
#define TPB_  288             // 1728 / 288 = exactly 6 iterations, no ragged tail

// Scratch: transposed partials, g_partials[j * B_ + b] (contiguous per joint)
__device__ float g_partials[BJ_];

// ---------------------------------------------------------------------------
// Kernel A: one block per (b,j) slice, 288 threads, exact 6-iter unrolled
// stream with last-use (__ldlu) loads -- strictly single-use data, so mark
// lines dead-on-read at L1 and evict-first at L2. PDL trigger at entry;
// weight load hoisted to overlap the stream.
// ---------------------------------------------------------------------------
__global__ __launch_bounds__(TPB_) void jmse_partial_kernel(
    const float* __restrict__ out,
    const float* __restrict__ tgt,
    const float* __restrict__ wgt)
{
    asm volatile("griddepcontrol.launch_dependents;");

    const int bj = blockIdx.x;

    // Hoisted scalar weight load: resolved long before the epilogue.
    float w_early = 0.0f;
    if (threadIdx.x == 0) w_early = __ldg(&wgt[bj]);

    const size_t base = (size_t)bj * HW_;
    const float4* __restrict__ o4 = (const float4*)(out + base);
    const float4* __restrict__ t4 = (const float4*)(tgt + base);

    // Two independent accumulator chains (even/odd unroll steps).
    float acc0 = 0.0f, acc1 = 0.0f;
    #pragma unroll
    for (int k = 0; k < 6; k++) {          // exact: 6 * 288 = 1728
        const int i = threadIdx.x + k * TPB_;
        float4 a = __ldlu(o4 + i);         // single-use: last-use policy
        float4 b = __ldlu(t4 + i);
        float d0 = a.x - b.x;
        float d1 = a.y - b.y;
        float d2 = a.z - b.z;
        float d3 = a.w - b.w;
        if (k & 1) {
            acc1 = fmaf(d0, d0, acc1);
            acc1 = fmaf(d1, d1, acc1);
            acc1 = fmaf(d2, d2, acc1);
            acc1 = fmaf(d3, d3, acc1);
        } else {
            acc0 = fmaf(d0, d0, acc0);
            acc0 = fmaf(d1, d1, acc0);
            acc0 = fmaf(d2, d2, acc0);
            acc0 = fmaf(d3, d3, acc0);
        }
    }
    float acc = acc0 + acc1;

    // warp reduce
    #pragma unroll
    for (int off = 16; off > 0; off >>= 1)
        acc += __shfl_xor_sync(0xFFFFFFFFu, acc, off);

    __shared__ float warp_sums[TPB_ / 32];   // 9 warps
    const int lane = threadIdx.x & 31;
    const int wid  = threadIdx.x >> 5;
    if (lane == 0) warp_sums[wid] = acc;
    __syncthreads();

    if (threadIdx.x == 0) {
        float s = 0.0f;
        #pragma unroll
        for (int w9 = 0; w9 < TPB_ / 32; w9++) s += warp_sums[w9];
        const int b = bj / J_;
        const int j = bj - b * J_;
        g_partials[j * B_ + b] = s * w_early * w_early;   // transposed store
    }
}

// ---------------------------------------------------------------------------
// Kernel B (PDL secondary): 17 warps, one per joint; contiguous float4 loads.
// topk prefetched before the parked wait (independent of A's data).
// ---------------------------------------------------------------------------
__global__ __launch_bounds__(544) void jmse_final_kernel(
    const int* __restrict__ topk_ptr,
    float* __restrict__ result)
{
    __shared__ float losses[J_];
    __shared__ int   s_k;
    const int wid  = threadIdx.x >> 5;   // 0..16
    const int lane = threadIdx.x & 31;

    // Prefetch top_k while parked: does not depend on kernel A's writes.
    if (threadIdx.x == 0) s_k = *topk_ptr;

    // Park until primary grid completes; its writes are then visible.
    asm volatile("griddepcontrol.wait;");

    if (wid < J_) {
        // 256 floats per joint = 64 float4, 2 per lane
        const float4* p4 = (const float4*)&g_partials[wid * B_];
        float4 a = p4[lane];
        float4 b = p4[lane + 32];
        float s = (a.x + a.y) + (a.z + a.w) + (b.x + b.y) + (b.z + b.w);
        #pragma unroll
        for (int off = 16; off > 0; off >>= 1)
            s += __shfl_xor_sync(0xFFFFFFFFu, s, off);
        if (lane == 0)
            losses[wid] = s * (1.0f / ((float)B_ * (float)HW_));
    }
    __syncthreads();

    if (threadIdx.x == 0) {
        const int k = s_k;
        float v[J_];
        #pragma unroll
        for (int j = 0; j < J_; j++) v[j] = losses[j];
        float sum = 0.0f;
        for (int s = 0; s < k; s++) {
            int   best_i = 0;
            float best_v = v[0];
            #pragma unroll
            for (int j = 1; j < J_; j++)
                if (v[j] > best_v) { best_v = v[j]; best_i = j; }
            sum += best_v;
            v[best_i] = -3.402823466e38f;
        }
        result[0] = sum / (float)k;
    }
}

// ---------------------------------------------------------------------------
extern "C" void kernel_launch(void* const* d_in, const int* in_sizes, int n_in,
                              void* d_out, int out_size)
{
    const float* out_t = (const float*)d_in[0];
    const float* tgt_t = (const float*)d_in[1];
    const float* wgt_t = (const float*)d_in[2];
    const int*   topk  = (const int*)d_in[3];
    float* res = (float*)d_out;

    jmse_partial_kernel<<<BJ_, TPB_>>>(out_t, tgt_t, wgt_t);

    cudaLaunchConfig_t cfg = {};
    cfg.gridDim  = dim3(1, 1, 1);
    cfg.blockDim = dim3(544, 1, 1);
    cfg.dynamicSmemBytes = 0;
    cfg.stream = 0;
    cudaLaunchAttribute attr[1];
    attr[0].id = cudaLaunchAttributeProgrammaticStreamSerialization;
    attr[0].val.programmaticStreamSerializationAllowed = 1;
    cfg.attrs = attr;
    cfg.numAttrs = 1;
    cudaLaunchKernelEx(&cfg, jmse_final_kernel, topk, res);
}